// round 11
// baseline (speedup 1.0000x reference)
#include <cuda_runtime.h>
#include <cstdint>
#include <cstddef>

#define EPS_ 1e-5f
#define KADA 0.1f

typedef unsigned long long ull;

// packed f32x2 helpers (FFMA2 path — sm_103a)
__device__ __forceinline__ ull pack2(float lo, float hi) {
    ull r; asm("mov.b64 %0, {%1, %2};" : "=l"(r) : "f"(lo), "f"(hi)); return r;
}
__device__ __forceinline__ void unpack2(ull v, float& lo, float& hi) {
    asm("mov.b64 {%0, %1}, %2;" : "=f"(lo), "=f"(hi) : "l"(v));
}
__device__ __forceinline__ ull fma2(ull a, ull b, ull c) {
    ull d; asm("fma.rn.f32x2 %0, %1, %2, %3;" : "=l"(d) : "l"(a), "l"(b), "l"(c)); return d;
}

// ---------------------------------------------------------------------------
// Persistent scratch
// ---------------------------------------------------------------------------
__device__ float d_h1[(size_t)2 * 96 * 96 * 96 * 16];   // only active sites valid
__device__ float d_h2[(size_t)2 * 48 * 48 * 48 * 32];
__device__ float d_h3[(size_t)2 * 48 * 48 * 48 * 32];
__device__ float d_h4[(size_t)2 * 24 * 24 * 24 * 64];
__device__ float d_h5[(size_t)2 * 24 * 24 * 24 * 64];
__device__ float d_m2[2 * 48 * 48 * 48];
__device__ float d_m3[2 * 24 * 24 * 24];
__device__ float d_pool[2 * 64];

// ---------------------------------------------------------------------------
// Mask downsample
// ---------------------------------------------------------------------------
template <int GIN, int GOUT>
__global__ void downsample_kernel(const float* __restrict__ mi, float* __restrict__ mo) {
    int i = blockIdx.x * blockDim.x + threadIdx.x;
    const int n = 2 * GOUT * GOUT * GOUT;
    if (i >= n) return;
    int x = i % GOUT; int t = i / GOUT;
    int y = t % GOUT; t /= GOUT;
    int z = t % GOUT; int b = t / GOUT;
    float v = 0.f;
    for (int kd = 0; kd < 3; kd++) {
        int iz = 2 * z + kd - 1; if (iz < 0 || iz >= GIN) continue;
        for (int kh = 0; kh < 3; kh++) {
            int iy = 2 * y + kh - 1; if (iy < 0 || iy >= GIN) continue;
            for (int kw = 0; kw < 3; kw++) {
                int ix = 2 * x + kw - 1; if (ix < 0 || ix >= GIN) continue;
                v = fmaxf(v, mi[((b * GIN + iz) * GIN + iy) * GIN + ix]);
            }
        }
    }
    mo[i] = v;
}

// ---------------------------------------------------------------------------
// Layer 1: SubMConv3d 1->16, fused AdaNorm+ReLU. Active voxels only.
// ---------------------------------------------------------------------------
__global__ void l1_kernel(const float* __restrict__ x, const float* __restrict__ mask,
                          const float* __restrict__ w1, const float* __restrict__ b1,
                          const float* __restrict__ g1) {
    __shared__ float ws[27 * 16];
    __shared__ float bs[16];
    __shared__ float gs[16];
    for (int j = threadIdx.x; j < 432; j += blockDim.x) ws[j] = w1[j];
    if (threadIdx.x < 16) { bs[threadIdx.x] = b1[threadIdx.x]; gs[threadIdx.x] = g1[threadIdx.x]; }
    __syncthreads();

    int i = blockIdx.x * blockDim.x + threadIdx.x;
    int xo = i % 96; int t = i / 96;
    int yo = t % 96; t /= 96;
    int zo = t % 96; int b = t / 96;

    float m = mask[i];
    if (m == 0.f) return;

    float acc[16];
#pragma unroll
    for (int c = 0; c < 16; c++) acc[c] = 0.f;

    for (int kd = 0; kd < 3; kd++) {
        int iz = zo + kd - 1; if (iz < 0 || iz >= 96) continue;
        for (int kh = 0; kh < 3; kh++) {
            int iy = yo + kh - 1; if (iy < 0 || iy >= 96) continue;
            for (int kw = 0; kw < 3; kw++) {
                int ix = xo + kw - 1; if (ix < 0 || ix >= 96) continue;
                float xv = x[((b * 96 + iz) * 96 + iy) * 96 + ix];
                if (xv != 0.f) {
                    int wb = ((kd * 3 + kh) * 3 + kw) * 16;
#pragma unroll
                    for (int c = 0; c < 16; c++) acc[c] += xv * ws[wb + c];
                }
            }
        }
    }
    float v[16]; float s = 0.f;
#pragma unroll
    for (int c = 0; c < 16; c++) { v[c] = acc[c] + bs[c]; s += v[c]; }
    float mean = s * (1.f / 16.f);
    float s2 = 0.f;
#pragma unroll
    for (int c = 0; c < 16; c++) { float d = v[c] - mean; s2 += d * d; }
    float r = rsqrtf(s2 * (1.f / 16.f) + EPS_);
    float4* out4 = reinterpret_cast<float4*>(d_h1 + (size_t)i * 16);
#pragma unroll
    for (int q = 0; q < 4; q++) {
        float4 o4;
        float xn0 = (v[q * 4 + 0] - mean) * r; o4.x = fmaxf(gs[q * 4 + 0] * (1.f - KADA * xn0) * xn0, 0.f);
        float xn1 = (v[q * 4 + 1] - mean) * r; o4.y = fmaxf(gs[q * 4 + 1] * (1.f - KADA * xn1) * xn1, 0.f);
        float xn2 = (v[q * 4 + 2] - mean) * r; o4.z = fmaxf(gs[q * 4 + 2] * (1.f - KADA * xn2) * xn2, 0.f);
        float xn3 = (v[q * 4 + 3] - mean) * r; o4.w = fmaxf(gs[q * 4 + 3] * (1.f - KADA * xn3) * xn3, 0.f);
        out4[q] = o4;
    }
}

// ---------------------------------------------------------------------------
// Layer 2: SparseConv3d s=2, 16->32, fused AdaNorm+ReLU, ballot tap discovery.
// ---------------------------------------------------------------------------
__global__ void l2_kernel(const float* __restrict__ mask, const float* __restrict__ w2,
                          const float* __restrict__ b2, const float* __restrict__ g2) {
    extern __shared__ float sm[];
    float* ws = sm;                 // [tap(27)][ci(16)][co(32)]
    float* bs = sm + 13824;
    float* gs = bs + 32;
    for (int j = threadIdx.x; j < 13824; j += blockDim.x) ws[j] = w2[j];
    if (threadIdx.x < 32) { bs[threadIdx.x] = b2[threadIdx.x]; gs[threadIdx.x] = g2[threadIdx.x]; }
    __syncthreads();

    int lane = threadIdx.x & 31;
    int warp = threadIdx.x >> 5;
    int gwarp = blockIdx.x * (blockDim.x >> 5) + warp;
    int nwarps = gridDim.x * (blockDim.x >> 5);

    int kd = lane / 9, kh = (lane / 3) % 3, kw = lane % 3;

    for (int v = gwarp; v < 2 * 48 * 48 * 48; v += nwarps) {
        int xo = v % 48; int t = v / 48;
        int yo = t % 48; t /= 48;
        int zo = t % 48; int b = t / 48;

        float mo = d_m2[v];
        float* out = d_h2 + (size_t)v * 32;
        if (mo == 0.f) { out[lane] = 0.f; continue; }

        int iz = 2 * zo + kd - 1, iy = 2 * yo + kh - 1, ix = 2 * xo + kw - 1;
        bool inb = (lane < 27) && (unsigned)iz < 96u && (unsigned)iy < 96u && (unsigned)ix < 96u;
        int ii = ((b * 96 + iz) * 96 + iy) * 96 + ix;
        float mv = inb ? mask[ii] : 0.f;
        unsigned bits = __ballot_sync(0xffffffffu, mv != 0.f);

        float acc = 0.f;
        while (bits) {
            int tap = __ffs(bits) - 1; bits &= bits - 1;
            int it = __shfl_sync(0xffffffffu, ii, tap);
            const float4* ip4 = reinterpret_cast<const float4*>(d_h1 + (size_t)it * 16);
            const float* wt = ws + tap * 512 + lane;
            float4 a0 = ip4[0], a1 = ip4[1], a2 = ip4[2], a3 = ip4[3];
            acc += a0.x * wt[0 * 32];  acc += a0.y * wt[1 * 32];
            acc += a0.z * wt[2 * 32];  acc += a0.w * wt[3 * 32];
            acc += a1.x * wt[4 * 32];  acc += a1.y * wt[5 * 32];
            acc += a1.z * wt[6 * 32];  acc += a1.w * wt[7 * 32];
            acc += a2.x * wt[8 * 32];  acc += a2.y * wt[9 * 32];
            acc += a2.z * wt[10 * 32]; acc += a2.w * wt[11 * 32];
            acc += a3.x * wt[12 * 32]; acc += a3.y * wt[13 * 32];
            acc += a3.z * wt[14 * 32]; acc += a3.w * wt[15 * 32];
        }
        float vv = acc + bs[lane];
        float s = vv;
#pragma unroll
        for (int off = 16; off > 0; off >>= 1) s += __shfl_xor_sync(0xffffffffu, s, off);
        float mean = s * (1.f / 32.f);
        float d = vv - mean;
        float s2 = d * d;
#pragma unroll
        for (int off = 16; off > 0; off >>= 1) s2 += __shfl_xor_sync(0xffffffffu, s2, off);
        float r = rsqrtf(s2 * (1.f / 32.f) + EPS_);
        float xn = d * r;
        out[lane] = fmaxf(gs[lane] * (1.f - KADA * xn) * xn, 0.f);
    }
}

// ---------------------------------------------------------------------------
// Generic conv (L3/L4/L5), FFMA2 with 4 voxels x CT couts per thread.
// Each LDS.64 weight pair feeds 4 fma2 (one per voxel accumulator).
// ---------------------------------------------------------------------------
template <int CIN, int GIN, int GOUT, int STRIDE, int CT>
__global__ void conv_kernel(const float* __restrict__ in, const float* __restrict__ w,
                            const float* __restrict__ bias, const float* __restrict__ mout,
                            float* __restrict__ out, int cout_total) {
    extern __shared__ float ws[];   // 9*CIN*CT per kd slice
    const int cobase = blockIdx.y * CT;
    int tid = threadIdx.x;
    int pid = blockIdx.x * blockDim.x + tid;
    const int GX4 = GOUT / 4;
    int xq = pid % GX4; int t = pid / GX4;
    int yo = t % GOUT; t /= GOUT;
    int zo = t % GOUT; int b = t / GOUT;
    int x0 = xq * 4;

    size_t vox0 = ((size_t)(b * GOUT + zo) * GOUT + yo) * GOUT + x0;
    float mk[4];
#pragma unroll
    for (int v = 0; v < 4; v++) mk[v] = mout[vox0 + v];
    bool act = (mk[0] != 0.f) || (mk[1] != 0.f) || (mk[2] != 0.f) || (mk[3] != 0.f);

    ull acc[4][CT / 2];
#pragma unroll
    for (int v = 0; v < 4; v++)
#pragma unroll
        for (int p = 0; p < CT / 2; p++) acc[v][p] = 0ULL;

    for (int kd = 0; kd < 3; kd++) {
        __syncthreads();
        {
            const int n = 9 * CIN * CT;
            for (int j = tid; j < n; j += blockDim.x) {
                int co = j % CT;
                int rest = j / CT;             // khw*CIN + ci
                int ci = rest % CIN;
                int khw = rest / CIN;
                ws[j] = w[((size_t)(kd * 9 + khw) * CIN + ci) * cout_total + cobase + co];
            }
        }
        __syncthreads();

        int iz = zo * STRIDE + kd - 1;
        if (act && iz >= 0 && iz < GIN) {
            for (int kh = 0; kh < 3; kh++) {
                int iy = yo * STRIDE + kh - 1; if (iy < 0 || iy >= GIN) continue;
                size_t rowbase = ((size_t)(b * GIN + iz) * GIN + iy) * GIN;
                for (int kw = 0; kw < 3; kw++) {
                    const float* wrow = ws + (kh * 3 + kw) * CIN * CT;
                    bool inb[4];
                    const float4* p4[4];
#pragma unroll
                    for (int v = 0; v < 4; v++) {
                        int ixv = x0 * STRIDE + v * STRIDE + kw - 1;
                        inb[v] = (ixv >= 0) && (ixv < GIN);
                        p4[v] = reinterpret_cast<const float4*>(in + (rowbase + (inb[v] ? ixv : 0)) * CIN);
                    }
                    const float4 z4 = make_float4(0.f, 0.f, 0.f, 0.f);
#pragma unroll 2
                    for (int ci4 = 0; ci4 < CIN / 4; ci4++) {
                        float4 a[4];
#pragma unroll
                        for (int v = 0; v < 4; v++) a[v] = inb[v] ? p4[v][ci4] : z4;
#pragma unroll
                        for (int j = 0; j < 4; j++) {
                            float c0 = (j == 0) ? a[0].x : (j == 1) ? a[0].y : (j == 2) ? a[0].z : a[0].w;
                            float c1 = (j == 0) ? a[1].x : (j == 1) ? a[1].y : (j == 2) ? a[1].z : a[1].w;
                            float c2 = (j == 0) ? a[2].x : (j == 1) ? a[2].y : (j == 2) ? a[2].z : a[2].w;
                            float c3 = (j == 0) ? a[3].x : (j == 1) ? a[3].y : (j == 2) ? a[3].z : a[3].w;
                            ull X0 = pack2(c0, c0);
                            ull X1 = pack2(c1, c1);
                            ull X2 = pack2(c2, c2);
                            ull X3 = pack2(c3, c3);
                            const ull* wr = reinterpret_cast<const ull*>(wrow + (ci4 * 4 + j) * CT);
#pragma unroll
                            for (int p = 0; p < CT / 2; p++) {
                                ull wp = wr[p];
                                acc[0][p] = fma2(X0, wp, acc[0][p]);
                                acc[1][p] = fma2(X1, wp, acc[1][p]);
                                acc[2][p] = fma2(X2, wp, acc[2][p]);
                                acc[3][p] = fma2(X3, wp, acc[3][p]);
                            }
                        }
                    }
                }
            }
        }
    }

    const float4 z4 = make_float4(0.f, 0.f, 0.f, 0.f);
#pragma unroll
    for (int v = 0; v < 4; v++) {
        float4* ov = reinterpret_cast<float4*>(out + (vox0 + v) * cout_total + cobase);
#pragma unroll
        for (int q = 0; q < CT / 4; q++) {
            float4 rr;
            unpack2(acc[v][q * 2 + 0], rr.x, rr.y);
            unpack2(acc[v][q * 2 + 1], rr.z, rr.w);
            rr.x += bias[cobase + q * 4 + 0];
            rr.y += bias[cobase + q * 4 + 1];
            rr.z += bias[cobase + q * 4 + 2];
            rr.w += bias[cobase + q * 4 + 3];
            ov[q] = (mk[v] != 0.f) ? rr : z4;
        }
    }
}

// ---------------------------------------------------------------------------
// In-place AdaNorm + ReLU over the channel axis
// ---------------------------------------------------------------------------
template <int C>
__global__ void adanorm_kernel(float* __restrict__ h, const float* __restrict__ g, int nvox) {
    int i = blockIdx.x * blockDim.x + threadIdx.x;
    if (i >= nvox) return;
    float4* p = reinterpret_cast<float4*>(h + (size_t)i * C);
    float v[C];
#pragma unroll
    for (int q = 0; q < C / 4; q++) {
        float4 a = p[q];
        v[q * 4 + 0] = a.x; v[q * 4 + 1] = a.y; v[q * 4 + 2] = a.z; v[q * 4 + 3] = a.w;
    }
    float s = 0.f;
#pragma unroll
    for (int c = 0; c < C; c++) s += v[c];
    float mean = s * (1.f / C);
    float s2 = 0.f;
#pragma unroll
    for (int c = 0; c < C; c++) { float d = v[c] - mean; s2 += d * d; }
    float r = rsqrtf(s2 * (1.f / C) + EPS_);
#pragma unroll
    for (int q = 0; q < C / 4; q++) {
        float4 a;
        float xn;
        xn = (v[q * 4 + 0] - mean) * r; a.x = fmaxf(g[q * 4 + 0] * (1.f - KADA * xn) * xn, 0.f);
        xn = (v[q * 4 + 1] - mean) * r; a.y = fmaxf(g[q * 4 + 1] * (1.f - KADA * xn) * xn, 0.f);
        xn = (v[q * 4 + 2] - mean) * r; a.z = fmaxf(g[q * 4 + 2] * (1.f - KADA * xn) * xn, 0.f);
        xn = (v[q * 4 + 3] - mean) * r; a.w = fmaxf(g[q * 4 + 3] * (1.f - KADA * xn) * xn, 0.f);
        p[q] = a;
    }
}

// ---------------------------------------------------------------------------
// Global masked max pool -> d_pool[2][64]
// ---------------------------------------------------------------------------
__global__ void pool_kernel() {
    int b = blockIdx.x;
    int c = threadIdx.x & 63;
    int grp = threadIdx.x >> 6;
    float best = -3.0e38f;
    for (int v = grp; v < 13824; v += 16) {
        float m = d_m3[b * 13824 + v];
        float hv = d_h5[((size_t)(b * 13824 + v)) * 64 + c];
        best = fmaxf(best, m > 0.f ? hv : -3.0e38f);
    }
    __shared__ float red[1024];
    red[threadIdx.x] = best;
    __syncthreads();
    for (int s = 8; s > 0; s >>= 1) {
        if (grp < s) red[grp * 64 + c] = fmaxf(red[grp * 64 + c], red[(grp + s) * 64 + c]);
        __syncthreads();
    }
    if (grp == 0) d_pool[b * 64 + c] = red[c];
}

// ---------------------------------------------------------------------------
// Head
// ---------------------------------------------------------------------------
__global__ void head_kernel(const float* __restrict__ wh, const float* __restrict__ bh,
                            const float* __restrict__ gh, float* __restrict__ out) {
    int t = threadIdx.x;
    int b = t >> 6;
    int f = t & 63;
    float s = bh[f];
    for (int ci = 0; ci < 64; ci++) s += d_pool[b * 64 + ci] * wh[ci * 64 + f];
    __shared__ float sh[128];
    sh[t] = s;
    __syncthreads();
    float sum = 0.f;
    for (int j = 0; j < 64; j++) sum += sh[b * 64 + j];
    float mean = sum * (1.f / 64.f);
    float var = 0.f;
    for (int j = 0; j < 64; j++) { float d = sh[b * 64 + j] - mean; var += d * d; }
    float r = rsqrtf(var * (1.f / 64.f) + EPS_);
    float xn = (s - mean) * r;
    out[t] = fmaxf(gh[f] * (1.f - KADA * xn) * xn, 0.f);
}

// ---------------------------------------------------------------------------
// Launch
// ---------------------------------------------------------------------------
extern "C" void kernel_launch(void* const* d_in, const int* in_sizes, int n_in,
                              void* d_out, int out_size) {
    const float* x    = (const float*)d_in[0];
    const float* mask = (const float*)d_in[1];
    const float* w1 = (const float*)d_in[2];
    const float* b1 = (const float*)d_in[3];
    const float* g1 = (const float*)d_in[4];
    const float* w2 = (const float*)d_in[5];
    const float* b2 = (const float*)d_in[6];
    const float* g2 = (const float*)d_in[7];
    const float* w3 = (const float*)d_in[8];
    const float* b3 = (const float*)d_in[9];
    const float* g3 = (const float*)d_in[10];
    const float* w4 = (const float*)d_in[11];
    const float* b4 = (const float*)d_in[12];
    const float* g4 = (const float*)d_in[13];
    const float* w5 = (const float*)d_in[14];
    const float* b5 = (const float*)d_in[15];
    const float* g5 = (const float*)d_in[16];
    const float* wh = (const float*)d_in[17];
    const float* bh = (const float*)d_in[18];
    const float* gh = (const float*)d_in[19];
    float* out = (float*)d_out;

    cudaFuncSetAttribute(l2_kernel, cudaFuncAttributeMaxDynamicSharedMemorySize, 56 * 1024);

    void *ph2, *ph3, *ph4, *ph5, *pm2, *pm3;
    cudaGetSymbolAddress(&ph2, d_h2);
    cudaGetSymbolAddress(&ph3, d_h3);
    cudaGetSymbolAddress(&ph4, d_h4);
    cudaGetSymbolAddress(&ph5, d_h5);
    cudaGetSymbolAddress(&pm2, d_m2);
    cudaGetSymbolAddress(&pm3, d_m3);

    // masks
    downsample_kernel<96, 48><<<(2 * 48 * 48 * 48 + 255) / 256, 256>>>(mask, (float*)pm2);
    downsample_kernel<48, 24><<<(2 * 24 * 24 * 24 + 255) / 256, 256>>>((const float*)pm2, (float*)pm3);

    // layer 1 (fused; active sites only)
    l1_kernel<<<2 * 96 * 96 * 96 / 128, 128>>>(x, mask, w1, b1, g1);

    // layer 2 (fused, ballot tap discovery)
    l2_kernel<<<592, 256, (13824 + 64) * 4>>>(mask, w2, b2, g2);

    // layer 3: 48^3, 32->32, s=1. 4 voxels/thread, CT=16 -> 432x2 blocks of 128
    conv_kernel<32, 48, 48, 1, 16><<<dim3(432, 2), 128, 9 * 32 * 16 * 4>>>(
        (const float*)ph2, w3, b3, (const float*)pm2, (float*)ph3, 32);
    adanorm_kernel<32><<<(2 * 48 * 48 * 48 + 255) / 256, 256>>>((float*)ph3, g3, 2 * 48 * 48 * 48);

    // layer 4: 48^3 -> 24^3, 32->64, s=2. 4 voxels/thread, CT=16 -> 108x4 blocks of 64
    conv_kernel<32, 48, 24, 2, 16><<<dim3(108, 4), 64, 9 * 32 * 16 * 4>>>(
        (const float*)ph3, w4, b4, (const float*)pm3, (float*)ph4, 64);
    adanorm_kernel<64><<<108, 256>>>((float*)ph4, g4, 2 * 24 * 24 * 24);

    // layer 5: 24^3, 64->64, s=1. 4 voxels/thread, CT=16 -> 108x4 blocks of 64
    conv_kernel<64, 24, 24, 1, 16><<<dim3(108, 4), 64, 9 * 64 * 16 * 4>>>(
        (const float*)ph4, w5, b5, (const float*)pm3, (float*)ph5, 64);
    adanorm_kernel<64><<<108, 256>>>((float*)ph5, g5, 2 * 24 * 24 * 24);

    // pool + head
    pool_kernel<<<2, 1024>>>();
    head_kernel<<<1, 128>>>(wh, bh, gh, out);
}

// round 12
// speedup vs baseline: 1.1146x; 1.1146x over previous
#include <cuda_runtime.h>
#include <cstdint>
#include <cstddef>

#define EPS_ 1e-5f
#define KADA 0.1f

typedef unsigned long long ull;

// packed f32x2 helpers (FFMA2 path — sm_103a)
__device__ __forceinline__ ull pack2(float lo, float hi) {
    ull r; asm("mov.b64 %0, {%1, %2};" : "=l"(r) : "f"(lo), "f"(hi)); return r;
}
__device__ __forceinline__ void unpack2(ull v, float& lo, float& hi) {
    asm("mov.b64 {%0, %1}, %2;" : "=f"(lo), "=f"(hi) : "l"(v));
}
__device__ __forceinline__ ull fma2(ull a, ull b, ull c) {
    ull d; asm("fma.rn.f32x2 %0, %1, %2, %3;" : "=l"(d) : "l"(a), "l"(b), "l"(c)); return d;
}

// ---------------------------------------------------------------------------
// Persistent scratch
// ---------------------------------------------------------------------------
__device__ float d_h1[(size_t)2 * 96 * 96 * 96 * 16];   // only active sites valid
__device__ float d_h2[(size_t)2 * 48 * 48 * 48 * 32];
__device__ float d_h3[(size_t)2 * 48 * 48 * 48 * 32];
__device__ float d_h4[(size_t)2 * 24 * 24 * 24 * 64];
__device__ float d_h5[(size_t)2 * 24 * 24 * 24 * 64];
__device__ float d_m2[2 * 48 * 48 * 48];
__device__ float d_m3[2 * 24 * 24 * 24];
__device__ float d_pool[2 * 64];

// ---------------------------------------------------------------------------
// Mask downsample
// ---------------------------------------------------------------------------
template <int GIN, int GOUT>
__global__ void downsample_kernel(const float* __restrict__ mi, float* __restrict__ mo) {
    int i = blockIdx.x * blockDim.x + threadIdx.x;
    const int n = 2 * GOUT * GOUT * GOUT;
    if (i >= n) return;
    int x = i % GOUT; int t = i / GOUT;
    int y = t % GOUT; t /= GOUT;
    int z = t % GOUT; int b = t / GOUT;
    float v = 0.f;
    for (int kd = 0; kd < 3; kd++) {
        int iz = 2 * z + kd - 1; if (iz < 0 || iz >= GIN) continue;
        for (int kh = 0; kh < 3; kh++) {
            int iy = 2 * y + kh - 1; if (iy < 0 || iy >= GIN) continue;
            for (int kw = 0; kw < 3; kw++) {
                int ix = 2 * x + kw - 1; if (ix < 0 || ix >= GIN) continue;
                v = fmaxf(v, mi[((b * GIN + iz) * GIN + iy) * GIN + ix]);
            }
        }
    }
    mo[i] = v;
}

// ---------------------------------------------------------------------------
// Layer 1: SubMConv3d 1->16, fused AdaNorm+ReLU. Active voxels only.
// ---------------------------------------------------------------------------
__global__ void l1_kernel(const float* __restrict__ x, const float* __restrict__ mask,
                          const float* __restrict__ w1, const float* __restrict__ b1,
                          const float* __restrict__ g1) {
    __shared__ float ws[27 * 16];
    __shared__ float bs[16];
    __shared__ float gs[16];
    for (int j = threadIdx.x; j < 432; j += blockDim.x) ws[j] = w1[j];
    if (threadIdx.x < 16) { bs[threadIdx.x] = b1[threadIdx.x]; gs[threadIdx.x] = g1[threadIdx.x]; }
    __syncthreads();

    int i = blockIdx.x * blockDim.x + threadIdx.x;
    int xo = i % 96; int t = i / 96;
    int yo = t % 96; t /= 96;
    int zo = t % 96; int b = t / 96;

    float m = mask[i];
    if (m == 0.f) return;

    float acc[16];
#pragma unroll
    for (int c = 0; c < 16; c++) acc[c] = 0.f;

    for (int kd = 0; kd < 3; kd++) {
        int iz = zo + kd - 1; if (iz < 0 || iz >= 96) continue;
        for (int kh = 0; kh < 3; kh++) {
            int iy = yo + kh - 1; if (iy < 0 || iy >= 96) continue;
            for (int kw = 0; kw < 3; kw++) {
                int ix = xo + kw - 1; if (ix < 0 || ix >= 96) continue;
                float xv = x[((b * 96 + iz) * 96 + iy) * 96 + ix];
                if (xv != 0.f) {
                    int wb = ((kd * 3 + kh) * 3 + kw) * 16;
#pragma unroll
                    for (int c = 0; c < 16; c++) acc[c] += xv * ws[wb + c];
                }
            }
        }
    }
    float v[16]; float s = 0.f;
#pragma unroll
    for (int c = 0; c < 16; c++) { v[c] = acc[c] + bs[c]; s += v[c]; }
    float mean = s * (1.f / 16.f);
    float s2 = 0.f;
#pragma unroll
    for (int c = 0; c < 16; c++) { float d = v[c] - mean; s2 += d * d; }
    float r = rsqrtf(s2 * (1.f / 16.f) + EPS_);
    float4* out4 = reinterpret_cast<float4*>(d_h1 + (size_t)i * 16);
#pragma unroll
    for (int q = 0; q < 4; q++) {
        float4 o4;
        float xn0 = (v[q * 4 + 0] - mean) * r; o4.x = fmaxf(gs[q * 4 + 0] * (1.f - KADA * xn0) * xn0, 0.f);
        float xn1 = (v[q * 4 + 1] - mean) * r; o4.y = fmaxf(gs[q * 4 + 1] * (1.f - KADA * xn1) * xn1, 0.f);
        float xn2 = (v[q * 4 + 2] - mean) * r; o4.z = fmaxf(gs[q * 4 + 2] * (1.f - KADA * xn2) * xn2, 0.f);
        float xn3 = (v[q * 4 + 3] - mean) * r; o4.w = fmaxf(gs[q * 4 + 3] * (1.f - KADA * xn3) * xn3, 0.f);
        out4[q] = o4;
    }
}

// ---------------------------------------------------------------------------
// Layer 2: SparseConv3d s=2, 16->32, fused AdaNorm+ReLU, ballot tap discovery.
// ---------------------------------------------------------------------------
__global__ void l2_kernel(const float* __restrict__ mask, const float* __restrict__ w2,
                          const float* __restrict__ b2, const float* __restrict__ g2) {
    extern __shared__ float sm[];
    float* ws = sm;                 // [tap(27)][ci(16)][co(32)]
    float* bs = sm + 13824;
    float* gs = bs + 32;
    for (int j = threadIdx.x; j < 13824; j += blockDim.x) ws[j] = w2[j];
    if (threadIdx.x < 32) { bs[threadIdx.x] = b2[threadIdx.x]; gs[threadIdx.x] = g2[threadIdx.x]; }
    __syncthreads();

    int lane = threadIdx.x & 31;
    int warp = threadIdx.x >> 5;
    int gwarp = blockIdx.x * (blockDim.x >> 5) + warp;
    int nwarps = gridDim.x * (blockDim.x >> 5);

    int kd = lane / 9, kh = (lane / 3) % 3, kw = lane % 3;

    for (int v = gwarp; v < 2 * 48 * 48 * 48; v += nwarps) {
        int xo = v % 48; int t = v / 48;
        int yo = t % 48; t /= 48;
        int zo = t % 48; int b = t / 48;

        float mo = d_m2[v];
        float* out = d_h2 + (size_t)v * 32;
        if (mo == 0.f) { out[lane] = 0.f; continue; }

        int iz = 2 * zo + kd - 1, iy = 2 * yo + kh - 1, ix = 2 * xo + kw - 1;
        bool inb = (lane < 27) && (unsigned)iz < 96u && (unsigned)iy < 96u && (unsigned)ix < 96u;
        int ii = ((b * 96 + iz) * 96 + iy) * 96 + ix;
        float mv = inb ? mask[ii] : 0.f;
        unsigned bits = __ballot_sync(0xffffffffu, mv != 0.f);

        float acc = 0.f;
        while (bits) {
            int tap = __ffs(bits) - 1; bits &= bits - 1;
            int it = __shfl_sync(0xffffffffu, ii, tap);
            const float4* ip4 = reinterpret_cast<const float4*>(d_h1 + (size_t)it * 16);
            const float* wt = ws + tap * 512 + lane;
            float4 a0 = ip4[0], a1 = ip4[1], a2 = ip4[2], a3 = ip4[3];
            acc += a0.x * wt[0 * 32];  acc += a0.y * wt[1 * 32];
            acc += a0.z * wt[2 * 32];  acc += a0.w * wt[3 * 32];
            acc += a1.x * wt[4 * 32];  acc += a1.y * wt[5 * 32];
            acc += a1.z * wt[6 * 32];  acc += a1.w * wt[7 * 32];
            acc += a2.x * wt[8 * 32];  acc += a2.y * wt[9 * 32];
            acc += a2.z * wt[10 * 32]; acc += a2.w * wt[11 * 32];
            acc += a3.x * wt[12 * 32]; acc += a3.y * wt[13 * 32];
            acc += a3.z * wt[14 * 32]; acc += a3.w * wt[15 * 32];
        }
        float vv = acc + bs[lane];
        float s = vv;
#pragma unroll
        for (int off = 16; off > 0; off >>= 1) s += __shfl_xor_sync(0xffffffffu, s, off);
        float mean = s * (1.f / 32.f);
        float d = vv - mean;
        float s2 = d * d;
#pragma unroll
        for (int off = 16; off > 0; off >>= 1) s2 += __shfl_xor_sync(0xffffffffu, s2, off);
        float r = rsqrtf(s2 * (1.f / 32.f) + EPS_);
        float xn = d * r;
        out[lane] = fmaxf(gs[lane] * (1.f - KADA * xn) * xn, 0.f);
    }
}

// ---------------------------------------------------------------------------
// Smem-staged conv (L3/L4/L5).
// Block = 128 threads = 2 y-rows x full-x x full-cout.
// Per (kd,kh) stage: weights slice + 2 input rows (halo zero-filled, values
// pre-duplicated as (v,v) 8B pairs) into smem. Inner loop: LDS.64 + fma2 only,
// no boundary branches.
// Thread tile: 6 x-positions x 4 couts (12 ull accumulators).
// ---------------------------------------------------------------------------
template <int CIN, int GIN, int GOUT, int STRIDE, int COUT>
__global__ __launch_bounds__(128) void conv_smem_kernel(
    const float* __restrict__ in, const float* __restrict__ w,
    const float* __restrict__ bias, const float* __restrict__ mout,
    float* __restrict__ out) {
    constexpr int XTC = GOUT / 6;          // x-tiles per row
    constexpr int CGC = COUT / 4;          // cout groups
    static_assert(XTC * CGC == 64, "row must be 64 threads");
    constexpr int SPAN = GIN + 2;
    constexpr int SPANP = (SPAN & 1) ? SPAN : SPAN + 1;   // odd pad
    constexpr int NIN = (STRIDE == 1) ? 8 : 13;

    extern __shared__ ull smem[];
    ull* sin = smem;                                   // [2][CIN][SPANP] (v,v) pairs
    float* sw = (float*)(smem + 2 * CIN * SPANP);      // [3][CIN][COUT]

    int tid = threadIdx.x;
    int row = tid >> 6;
    int r = tid & 63;
    int xt = r % XTC, cg = r / XTC;
    int x0 = xt * 6, co0 = cg * 4;

    int bid = blockIdx.x;
    int yp = bid % (GOUT / 2);
    int z = (bid / (GOUT / 2)) % GOUT;
    int b = bid / ((GOUT / 2) * GOUT);
    int y0 = yp * 2;

    ull acc[6][2];
#pragma unroll
    for (int dx = 0; dx < 6; dx++) { acc[dx][0] = 0ULL; acc[dx][1] = 0ULL; }

    for (int kd = 0; kd < 3; kd++) {
        int iz = z * STRIDE + kd - 1;
        if (iz < 0 || iz >= GIN) continue;              // uniform across block
        for (int kh = 0; kh < 3; kh++) {
            __syncthreads();
            // stage weights: [kw][ci][co]
            for (int j = tid; j < 3 * CIN * COUT; j += 128) {
                int co = j % COUT;
                int rest = j / COUT;
                int ci = rest % CIN;
                int kw = rest / CIN;
                sw[j] = w[((size_t)((kd * 3 + kh) * 3 + kw) * CIN + ci) * COUT + co];
            }
            // stage 2 input rows (zero-filled OOB), duplicated pairs
            int iyb = y0 * STRIDE + kh - 1;
            for (int j = tid; j < 2 * CIN * SPAN; j += 128) {
                int rw = j / (CIN * SPAN);
                int rr = j % (CIN * SPAN);
                int ci = rr % CIN;
                int xp = rr / CIN;
                int ix = xp - 1;
                int iy = iyb + rw * STRIDE;
                float v = 0.f;
                if ((unsigned)iy < (unsigned)GIN && (unsigned)ix < (unsigned)GIN)
                    v = in[(((size_t)(b * GIN + iz) * GIN + iy) * GIN + ix) * CIN + ci];
                sin[rw * (CIN * SPANP) + ci * SPANP + xp] = pack2(v, v);
            }
            __syncthreads();

            const ull* inr = sin + row * (CIN * SPANP);
#pragma unroll 2
            for (int ci = 0; ci < CIN; ci++) {
                const ull* ip = inr + ci * SPANP + x0 * STRIDE;
                ull pk[NIN];
#pragma unroll
                for (int k = 0; k < NIN; k++) pk[k] = ip[k];
#pragma unroll
                for (int kw = 0; kw < 3; kw++) {
                    const ull* wv = (const ull*)(sw + (kw * CIN + ci) * COUT + co0);
                    ull w0 = wv[0], w1 = wv[1];
#pragma unroll
                    for (int dx = 0; dx < 6; dx++) {
                        acc[dx][0] = fma2(pk[dx * STRIDE + kw], w0, acc[dx][0]);
                        acc[dx][1] = fma2(pk[dx * STRIDE + kw], w1, acc[dx][1]);
                    }
                }
            }
        }
    }

    // epilogue: +bias, mask, store
    float4 b4 = *(const float4*)(bias + co0);
    const float4 z4 = make_float4(0.f, 0.f, 0.f, 0.f);
    size_t vb = (((size_t)b * GOUT + z) * GOUT + (y0 + row)) * (size_t)GOUT + x0;
#pragma unroll
    for (int dx = 0; dx < 6; dx++) {
        float m = mout[vb + dx];
        float4 rr;
        unpack2(acc[dx][0], rr.x, rr.y);
        unpack2(acc[dx][1], rr.z, rr.w);
        rr.x += b4.x; rr.y += b4.y; rr.z += b4.z; rr.w += b4.w;
        *reinterpret_cast<float4*>(out + (vb + dx) * COUT + co0) = (m != 0.f) ? rr : z4;
    }
}

// ---------------------------------------------------------------------------
// In-place AdaNorm + ReLU over the channel axis
// ---------------------------------------------------------------------------
template <int C>
__global__ void adanorm_kernel(float* __restrict__ h, const float* __restrict__ g, int nvox) {
    int i = blockIdx.x * blockDim.x + threadIdx.x;
    if (i >= nvox) return;
    float4* p = reinterpret_cast<float4*>(h + (size_t)i * C);
    float v[C];
#pragma unroll
    for (int q = 0; q < C / 4; q++) {
        float4 a = p[q];
        v[q * 4 + 0] = a.x; v[q * 4 + 1] = a.y; v[q * 4 + 2] = a.z; v[q * 4 + 3] = a.w;
    }
    float s = 0.f;
#pragma unroll
    for (int c = 0; c < C; c++) s += v[c];
    float mean = s * (1.f / C);
    float s2 = 0.f;
#pragma unroll
    for (int c = 0; c < C; c++) { float d = v[c] - mean; s2 += d * d; }
    float r = rsqrtf(s2 * (1.f / C) + EPS_);
#pragma unroll
    for (int q = 0; q < C / 4; q++) {
        float4 a;
        float xn;
        xn = (v[q * 4 + 0] - mean) * r; a.x = fmaxf(g[q * 4 + 0] * (1.f - KADA * xn) * xn, 0.f);
        xn = (v[q * 4 + 1] - mean) * r; a.y = fmaxf(g[q * 4 + 1] * (1.f - KADA * xn) * xn, 0.f);
        xn = (v[q * 4 + 2] - mean) * r; a.z = fmaxf(g[q * 4 + 2] * (1.f - KADA * xn) * xn, 0.f);
        xn = (v[q * 4 + 3] - mean) * r; a.w = fmaxf(g[q * 4 + 3] * (1.f - KADA * xn) * xn, 0.f);
        p[q] = a;
    }
}

// ---------------------------------------------------------------------------
// Global masked max pool -> d_pool[2][64]
// ---------------------------------------------------------------------------
__global__ void pool_kernel() {
    int b = blockIdx.x;
    int c = threadIdx.x & 63;
    int grp = threadIdx.x >> 6;
    float best = -3.0e38f;
    for (int v = grp; v < 13824; v += 16) {
        float m = d_m3[b * 13824 + v];
        float hv = d_h5[((size_t)(b * 13824 + v)) * 64 + c];
        best = fmaxf(best, m > 0.f ? hv : -3.0e38f);
    }
    __shared__ float red[1024];
    red[threadIdx.x] = best;
    __syncthreads();
    for (int s = 8; s > 0; s >>= 1) {
        if (grp < s) red[grp * 64 + c] = fmaxf(red[grp * 64 + c], red[(grp + s) * 64 + c]);
        __syncthreads();
    }
    if (grp == 0) d_pool[b * 64 + c] = red[c];
}

// ---------------------------------------------------------------------------
// Head
// ---------------------------------------------------------------------------
__global__ void head_kernel(const float* __restrict__ wh, const float* __restrict__ bh,
                            const float* __restrict__ gh, float* __restrict__ out) {
    int t = threadIdx.x;
    int b = t >> 6;
    int f = t & 63;
    float s = bh[f];
    for (int ci = 0; ci < 64; ci++) s += d_pool[b * 64 + ci] * wh[ci * 64 + f];
    __shared__ float sh[128];
    sh[t] = s;
    __syncthreads();
    float sum = 0.f;
    for (int j = 0; j < 64; j++) sum += sh[b * 64 + j];
    float mean = sum * (1.f / 64.f);
    float var = 0.f;
    for (int j = 0; j < 64; j++) { float d = sh[b * 64 + j] - mean; var += d * d; }
    float r = rsqrtf(var * (1.f / 64.f) + EPS_);
    float xn = (s - mean) * r;
    out[t] = fmaxf(gh[f] * (1.f - KADA * xn) * xn, 0.f);
}

// ---------------------------------------------------------------------------
// Launch
// ---------------------------------------------------------------------------
extern "C" void kernel_launch(void* const* d_in, const int* in_sizes, int n_in,
                              void* d_out, int out_size) {
    const float* x    = (const float*)d_in[0];
    const float* mask = (const float*)d_in[1];
    const float* w1 = (const float*)d_in[2];
    const float* b1 = (const float*)d_in[3];
    const float* g1 = (const float*)d_in[4];
    const float* w2 = (const float*)d_in[5];
    const float* b2 = (const float*)d_in[6];
    const float* g2 = (const float*)d_in[7];
    const float* w3 = (const float*)d_in[8];
    const float* b3 = (const float*)d_in[9];
    const float* g3 = (const float*)d_in[10];
    const float* w4 = (const float*)d_in[11];
    const float* b4 = (const float*)d_in[12];
    const float* g4 = (const float*)d_in[13];
    const float* w5 = (const float*)d_in[14];
    const float* b5 = (const float*)d_in[15];
    const float* g5 = (const float*)d_in[16];
    const float* wh = (const float*)d_in[17];
    const float* bh = (const float*)d_in[18];
    const float* gh = (const float*)d_in[19];
    float* out = (float*)d_out;

    cudaFuncSetAttribute(l2_kernel, cudaFuncAttributeMaxDynamicSharedMemorySize, 56 * 1024);
    cudaFuncSetAttribute(conv_smem_kernel<32, 48, 48, 1, 32>,
                         cudaFuncAttributeMaxDynamicSharedMemorySize, 40 * 1024);
    cudaFuncSetAttribute(conv_smem_kernel<32, 48, 24, 2, 64>,
                         cudaFuncAttributeMaxDynamicSharedMemorySize, 52 * 1024);
    cudaFuncSetAttribute(conv_smem_kernel<64, 24, 24, 1, 64>,
                         cudaFuncAttributeMaxDynamicSharedMemorySize, 78 * 1024);

    void *ph2, *ph3, *ph4, *ph5, *pm2, *pm3;
    cudaGetSymbolAddress(&ph2, d_h2);
    cudaGetSymbolAddress(&ph3, d_h3);
    cudaGetSymbolAddress(&ph4, d_h4);
    cudaGetSymbolAddress(&ph5, d_h5);
    cudaGetSymbolAddress(&pm2, d_m2);
    cudaGetSymbolAddress(&pm3, d_m3);

    // masks
    downsample_kernel<96, 48><<<(2 * 48 * 48 * 48 + 255) / 256, 256>>>(mask, (float*)pm2);
    downsample_kernel<48, 24><<<(2 * 24 * 24 * 24 + 255) / 256, 256>>>((const float*)pm2, (float*)pm3);

    // layer 1 (fused; active sites only)
    l1_kernel<<<2 * 96 * 96 * 96 / 128, 128>>>(x, mask, w1, b1, g1);

    // layer 2 (fused, ballot tap discovery)
    l2_kernel<<<592, 256, (13824 + 64) * 4>>>(mask, w2, b2, g2);

    // smem sizes for staged convs
    constexpr int SM3 = (2 * 32 * 51) * 8 + (3 * 32 * 32) * 4;   // 38400
    constexpr int SM4 = (2 * 32 * 51) * 8 + (3 * 32 * 64) * 4;   // 50688
    constexpr int SM5 = (2 * 64 * 27) * 8 + (3 * 64 * 64) * 4;   // 76800

    // layer 3: 48^3, 32->32, s=1.  blocks = 24 ypairs * 48 z * 2 b = 2304
    conv_smem_kernel<32, 48, 48, 1, 32><<<24 * 48 * 2, 128, SM3>>>(
        (const float*)ph2, w3, b3, (const float*)pm2, (float*)ph3);
    adanorm_kernel<32><<<(2 * 48 * 48 * 48 + 255) / 256, 256>>>((float*)ph3, g3, 2 * 48 * 48 * 48);

    // layer 4: 48^3 -> 24^3, 32->64, s=2.  blocks = 12 * 24 * 2 = 576
    conv_smem_kernel<32, 48, 24, 2, 64><<<12 * 24 * 2, 128, SM4>>>(
        (const float*)ph3, w4, b4, (const float*)pm3, (float*)ph4);
    adanorm_kernel<64><<<108, 256>>>((float*)ph4, g4, 2 * 24 * 24 * 24);

    // layer 5: 24^3, 64->64, s=1.  blocks = 12 * 24 * 2 = 576
    conv_smem_kernel<64, 24, 24, 1, 64><<<12 * 24 * 2, 128, SM5>>>(
        (const float*)ph4, w5, b5, (const float*)pm3, (float*)ph5);
    adanorm_kernel<64><<<108, 256>>>((float*)ph5, g5, 2 * 24 * 24 * 24);

    // pool + head
    pool_kernel<<<2, 1024>>>();
    head_kernel<<<1, 128>>>(wh, bh, gh, out);
}

// round 14
// speedup vs baseline: 1.2114x; 1.0868x over previous
#include <cuda_runtime.h>
#include <cstdint>
#include <cstddef>

#define EPS_ 1e-5f
#define KADA 0.1f

typedef unsigned long long ull;

// packed f32x2 helpers (FFMA2 path — sm_103a)
__device__ __forceinline__ ull pack2(float lo, float hi) {
    ull r; asm("mov.b64 %0, {%1, %2};" : "=l"(r) : "f"(lo), "f"(hi)); return r;
}
__device__ __forceinline__ void unpack2(ull v, float& lo, float& hi) {
    asm("mov.b64 {%0, %1}, %2;" : "=f"(lo), "=f"(hi) : "l"(v));
}
__device__ __forceinline__ ull fma2(ull a, ull b, ull c) {
    ull d; asm("fma.rn.f32x2 %0, %1, %2, %3;" : "=l"(d) : "l"(a), "l"(b), "l"(c)); return d;
}

// ---------------------------------------------------------------------------
// Persistent scratch
// ---------------------------------------------------------------------------
__device__ float d_h1[(size_t)2 * 96 * 96 * 96 * 16];   // only active sites valid
__device__ float d_h2[(size_t)2 * 48 * 48 * 48 * 32];
__device__ float d_h3[(size_t)2 * 48 * 48 * 48 * 32];
__device__ float d_h4[(size_t)2 * 24 * 24 * 24 * 64];
__device__ float d_h5[(size_t)2 * 24 * 24 * 24 * 64];
__device__ float d_m2[2 * 48 * 48 * 48];
__device__ float d_m3[2 * 24 * 24 * 24];
__device__ float d_pool[2 * 64];

// ---------------------------------------------------------------------------
// Mask downsample
// ---------------------------------------------------------------------------
template <int GIN, int GOUT>
__global__ void downsample_kernel(const float* __restrict__ mi, float* __restrict__ mo) {
    int i = blockIdx.x * blockDim.x + threadIdx.x;
    const int n = 2 * GOUT * GOUT * GOUT;
    if (i >= n) return;
    int x = i % GOUT; int t = i / GOUT;
    int y = t % GOUT; t /= GOUT;
    int z = t % GOUT; int b = t / GOUT;
    float v = 0.f;
    for (int kd = 0; kd < 3; kd++) {
        int iz = 2 * z + kd - 1; if (iz < 0 || iz >= GIN) continue;
        for (int kh = 0; kh < 3; kh++) {
            int iy = 2 * y + kh - 1; if (iy < 0 || iy >= GIN) continue;
            for (int kw = 0; kw < 3; kw++) {
                int ix = 2 * x + kw - 1; if (ix < 0 || ix >= GIN) continue;
                v = fmaxf(v, mi[((b * GIN + iz) * GIN + iy) * GIN + ix]);
            }
        }
    }
    mo[i] = v;
}

// ---------------------------------------------------------------------------
// Layer 1: SubMConv3d 1->16, fused AdaNorm+ReLU. Active voxels only.
// ---------------------------------------------------------------------------
__global__ void l1_kernel(const float* __restrict__ x, const float* __restrict__ mask,
                          const float* __restrict__ w1, const float* __restrict__ b1,
                          const float* __restrict__ g1) {
    __shared__ float ws[27 * 16];
    __shared__ float bs[16];
    __shared__ float gs[16];
    for (int j = threadIdx.x; j < 432; j += blockDim.x) ws[j] = w1[j];
    if (threadIdx.x < 16) { bs[threadIdx.x] = b1[threadIdx.x]; gs[threadIdx.x] = g1[threadIdx.x]; }
    __syncthreads();

    int i = blockIdx.x * blockDim.x + threadIdx.x;
    int xo = i % 96; int t = i / 96;
    int yo = t % 96; t /= 96;
    int zo = t % 96; int b = t / 96;

    float m = mask[i];
    if (m == 0.f) return;

    float acc[16];
#pragma unroll
    for (int c = 0; c < 16; c++) acc[c] = 0.f;

    for (int kd = 0; kd < 3; kd++) {
        int iz = zo + kd - 1; if (iz < 0 || iz >= 96) continue;
        for (int kh = 0; kh < 3; kh++) {
            int iy = yo + kh - 1; if (iy < 0 || iy >= 96) continue;
            for (int kw = 0; kw < 3; kw++) {
                int ix = xo + kw - 1; if (ix < 0 || ix >= 96) continue;
                float xv = x[((b * 96 + iz) * 96 + iy) * 96 + ix];
                if (xv != 0.f) {
                    int wb = ((kd * 3 + kh) * 3 + kw) * 16;
#pragma unroll
                    for (int c = 0; c < 16; c++) acc[c] += xv * ws[wb + c];
                }
            }
        }
    }
    float v[16]; float s = 0.f;
#pragma unroll
    for (int c = 0; c < 16; c++) { v[c] = acc[c] + bs[c]; s += v[c]; }
    float mean = s * (1.f / 16.f);
    float s2 = 0.f;
#pragma unroll
    for (int c = 0; c < 16; c++) { float d = v[c] - mean; s2 += d * d; }
    float r = rsqrtf(s2 * (1.f / 16.f) + EPS_);
    float4* out4 = reinterpret_cast<float4*>(d_h1 + (size_t)i * 16);
#pragma unroll
    for (int q = 0; q < 4; q++) {
        float4 o4;
        float xn0 = (v[q * 4 + 0] - mean) * r; o4.x = fmaxf(gs[q * 4 + 0] * (1.f - KADA * xn0) * xn0, 0.f);
        float xn1 = (v[q * 4 + 1] - mean) * r; o4.y = fmaxf(gs[q * 4 + 1] * (1.f - KADA * xn1) * xn1, 0.f);
        float xn2 = (v[q * 4 + 2] - mean) * r; o4.z = fmaxf(gs[q * 4 + 2] * (1.f - KADA * xn2) * xn2, 0.f);
        float xn3 = (v[q * 4 + 3] - mean) * r; o4.w = fmaxf(gs[q * 4 + 3] * (1.f - KADA * xn3) * xn3, 0.f);
        out4[q] = o4;
    }
}

// ---------------------------------------------------------------------------
// Layer 2 helper: warp AdaNorm+ReLU over 32 channels, store.
// ---------------------------------------------------------------------------
__device__ __forceinline__ void l2_norm_store(float acc, const float* bs, const float* gs,
                                              int lane, float* out) {
    float vv = acc + bs[lane];
    float s = vv;
#pragma unroll
    for (int off = 16; off > 0; off >>= 1) s += __shfl_xor_sync(0xffffffffu, s, off);
    float mean = s * (1.f / 32.f);
    float d = vv - mean;
    float s2 = d * d;
#pragma unroll
    for (int off = 16; off > 0; off >>= 1) s2 += __shfl_xor_sync(0xffffffffu, s2, off);
    float r = rsqrtf(s2 * (1.f / 32.f) + EPS_);
    float xn = d * r;
    out[lane] = fmaxf(gs[lane] * (1.f - KADA * xn) * xn, 0.f);
}

// ---------------------------------------------------------------------------
// Layer 2: SparseConv3d s=2, 16->32, fused AdaNorm+ReLU, ballot tap discovery.
// Two voxels per warp iteration for MLP on the latency-critical gathers.
// ---------------------------------------------------------------------------
__global__ void l2_kernel(const float* __restrict__ mask, const float* __restrict__ w2,
                          const float* __restrict__ b2, const float* __restrict__ g2) {
    extern __shared__ float sm[];
    float* ws = sm;                 // [tap(27)][ci(16)][co(32)]
    float* bs = sm + 13824;
    float* gs = bs + 32;
    for (int j = threadIdx.x; j < 13824; j += blockDim.x) ws[j] = w2[j];
    if (threadIdx.x < 32) { bs[threadIdx.x] = b2[threadIdx.x]; gs[threadIdx.x] = g2[threadIdx.x]; }
    __syncthreads();

    int lane = threadIdx.x & 31;
    int warp = threadIdx.x >> 5;
    int gwarp = blockIdx.x * (blockDim.x >> 5) + warp;
    int nwarps = gridDim.x * (blockDim.x >> 5);

    int kd = lane / 9, kh = (lane / 3) % 3, kw = lane % 3;
    const int NV = 2 * 48 * 48 * 48;

    for (int v0 = gwarp; v0 < NV; v0 += 2 * nwarps) {
        int v1 = v0 + nwarps;
        bool has1 = v1 < NV;
        float mo0 = d_m2[v0];
        float mo1 = has1 ? d_m2[v1] : 0.f;
        bool a0 = (mo0 != 0.f);
        bool a1 = (mo1 != 0.f);
        float* out0 = d_h2 + (size_t)v0 * 32;
        float* out1 = d_h2 + (size_t)v1 * 32;

        unsigned bits0 = 0, bits1 = 0;
        int ii0 = 0, ii1 = 0;
        if (a0) {
            int xo = v0 % 48; int t = v0 / 48;
            int yo = t % 48; t /= 48;
            int zo = t % 48; int b = t / 48;
            int iz = 2 * zo + kd - 1, iy = 2 * yo + kh - 1, ix = 2 * xo + kw - 1;
            bool inb = (lane < 27) && (unsigned)iz < 96u && (unsigned)iy < 96u && (unsigned)ix < 96u;
            ii0 = ((b * 96 + iz) * 96 + iy) * 96 + ix;
            float mv = inb ? mask[ii0] : 0.f;
            bits0 = __ballot_sync(0xffffffffu, mv != 0.f);
        } else {
            out0[lane] = 0.f;
        }
        if (a1) {
            int xo = v1 % 48; int t = v1 / 48;
            int yo = t % 48; t /= 48;
            int zo = t % 48; int b = t / 48;
            int iz = 2 * zo + kd - 1, iy = 2 * yo + kh - 1, ix = 2 * xo + kw - 1;
            bool inb = (lane < 27) && (unsigned)iz < 96u && (unsigned)iy < 96u && (unsigned)ix < 96u;
            ii1 = ((b * 96 + iz) * 96 + iy) * 96 + ix;
            float mv = inb ? mask[ii1] : 0.f;
            bits1 = __ballot_sync(0xffffffffu, mv != 0.f);
        } else if (has1) {
            out1[lane] = 0.f;
        }

        float acc0 = 0.f, acc1 = 0.f;
        while (bits0 | bits1) {
            int t0 = -1, t1 = -1;
            float4 x00, x01, x02, x03, x10, x11, x12, x13;
            if (bits0) {
                t0 = __ffs(bits0) - 1; bits0 &= bits0 - 1;
                int it = __shfl_sync(0xffffffffu, ii0, t0);
                const float4* p = reinterpret_cast<const float4*>(d_h1 + (size_t)it * 16);
                x00 = p[0]; x01 = p[1]; x02 = p[2]; x03 = p[3];
            }
            if (bits1) {
                t1 = __ffs(bits1) - 1; bits1 &= bits1 - 1;
                int it = __shfl_sync(0xffffffffu, ii1, t1);
                const float4* p = reinterpret_cast<const float4*>(d_h1 + (size_t)it * 16);
                x10 = p[0]; x11 = p[1]; x12 = p[2]; x13 = p[3];
            }
            if (t0 >= 0) {
                const float* wt = ws + t0 * 512 + lane;
                acc0 += x00.x * wt[0 * 32];  acc0 += x00.y * wt[1 * 32];
                acc0 += x00.z * wt[2 * 32];  acc0 += x00.w * wt[3 * 32];
                acc0 += x01.x * wt[4 * 32];  acc0 += x01.y * wt[5 * 32];
                acc0 += x01.z * wt[6 * 32];  acc0 += x01.w * wt[7 * 32];
                acc0 += x02.x * wt[8 * 32];  acc0 += x02.y * wt[9 * 32];
                acc0 += x02.z * wt[10 * 32]; acc0 += x02.w * wt[11 * 32];
                acc0 += x03.x * wt[12 * 32]; acc0 += x03.y * wt[13 * 32];
                acc0 += x03.z * wt[14 * 32]; acc0 += x03.w * wt[15 * 32];
            }
            if (t1 >= 0) {
                const float* wt = ws + t1 * 512 + lane;
                acc1 += x10.x * wt[0 * 32];  acc1 += x10.y * wt[1 * 32];
                acc1 += x10.z * wt[2 * 32];  acc1 += x10.w * wt[3 * 32];
                acc1 += x11.x * wt[4 * 32];  acc1 += x11.y * wt[5 * 32];
                acc1 += x11.z * wt[6 * 32];  acc1 += x11.w * wt[7 * 32];
                acc1 += x12.x * wt[8 * 32];  acc1 += x12.y * wt[9 * 32];
                acc1 += x12.z * wt[10 * 32]; acc1 += x12.w * wt[11 * 32];
                acc1 += x13.x * wt[12 * 32]; acc1 += x13.y * wt[13 * 32];
                acc1 += x13.z * wt[14 * 32]; acc1 += x13.w * wt[15 * 32];
            }
        }
        if (a0) l2_norm_store(acc0, bs, gs, lane, out0);
        if (a1) l2_norm_store(acc1, bs, gs, lane, out1);
    }
}

// ---------------------------------------------------------------------------
// conv3 (48^3, 32->32, s=1), per-kd staging, fused AdaNorm+ReLU.
// Block = 128 thr = 2 y-rows x (8 x-tiles x 8 cout-groups).
// Per kd: ONE staging phase (4 input rows + all 9 weight slices), 2 barriers.
// ---------------------------------------------------------------------------
__global__ __launch_bounds__(128) void conv3_kernel(
    const float* __restrict__ in, const float* __restrict__ w,
    const float* __restrict__ bias, const float* __restrict__ gvec,
    const float* __restrict__ mout, float* __restrict__ out) {
    constexpr int G = 48, CIN = 32, COUT = 32;
    constexpr int SPANP = 51;                     // 50 used, odd pad
    extern __shared__ ull smem[];
    ull* sinp = smem;                             // [4][CIN][SPANP] pairs = 52224 B
    float* sw = (float*)(smem + 4 * CIN * SPANP); // [9][CIN][COUT]  = 36864 B
    float* red = (float*)smem;                    // epilogue overlay (6 KB)

    int tid = threadIdx.x;
    int row = tid >> 6;          // 0..1
    int r = tid & 63;
    int xt = r % 8, cg = r / 8;  // 6 x per thread, 4 couts
    int x0 = xt * 6, co0 = cg * 4;

    int bid = blockIdx.x;
    int yp = bid % 24;
    int z = (bid / 24) % G;
    int b = bid / (24 * G);
    int y0 = yp * 2;

    size_t vb = (((size_t)b * G + z) * G + (y0 + row)) * (size_t)G + x0;
    bool act = false;
#pragma unroll
    for (int dx = 0; dx < 6; dx++) act |= (mout[vb + dx] != 0.f);

    ull acc[6][2];
#pragma unroll
    for (int dx = 0; dx < 6; dx++) { acc[dx][0] = 0ULL; acc[dx][1] = 0ULL; }

    for (int kd = 0; kd < 3; kd++) {
        int iz = z + kd - 1;
        if (iz < 0 || iz >= G) continue;          // block-uniform
        __syncthreads();
        // stage all 9 weight slices for this kd (float4)
        for (int j = tid; j < 9 * CIN * (COUT / 4); j += 128) {
            int co4 = j % 8;
            int ci = (j / 8) % CIN;
            int khw = j / 256;
            float4 wv = *reinterpret_cast<const float4*>(
                w + ((size_t)(kd * 9 + khw) * CIN + ci) * COUT + co4 * 4);
            *reinterpret_cast<float4*>(sw + (khw * CIN + ci) * COUT + co4 * 4) = wv;
        }
        // stage 4 input rows (iy = y0-1 .. y0+2), zero-filled OOB, paired
        for (int j = tid; j < 4 * 50 * 8; j += 128) {
            int ci4 = j % 8;
            int xp = (j / 8) % 50;
            int jr = j / 400;
            int iy = y0 - 1 + jr;
            int ix = xp - 1;
            float4 v4 = make_float4(0.f, 0.f, 0.f, 0.f);
            if ((unsigned)iy < (unsigned)G && (unsigned)ix < (unsigned)G)
                v4 = *reinterpret_cast<const float4*>(
                    in + (((size_t)(b * G + iz) * G + iy) * G + ix) * CIN + ci4 * 4);
            ull* dst = sinp + (jr * CIN + ci4 * 4) * SPANP + xp;
            dst[0 * SPANP] = pack2(v4.x, v4.x);
            dst[1 * SPANP] = pack2(v4.y, v4.y);
            dst[2 * SPANP] = pack2(v4.z, v4.z);
            dst[3 * SPANP] = pack2(v4.w, v4.w);
        }
        __syncthreads();

        if (!act) continue;
#pragma unroll
        for (int kh = 0; kh < 3; kh++) {
            const ull* inr = sinp + (row + kh) * CIN * SPANP;
#pragma unroll 2
            for (int ci = 0; ci < CIN; ci++) {
                const ull* ip = inr + ci * SPANP + x0;
                ull pk[8];
#pragma unroll
                for (int k = 0; k < 8; k++) pk[k] = ip[k];
#pragma unroll
                for (int kw = 0; kw < 3; kw++) {
                    const ull* wv = (const ull*)(sw + ((kh * 3 + kw) * CIN + ci) * COUT + co0);
                    ull w0 = wv[0], w1 = wv[1];
#pragma unroll
                    for (int dx = 0; dx < 6; dx++) {
                        acc[dx][0] = fma2(pk[dx + kw], w0, acc[dx][0]);
                        acc[dx][1] = fma2(pk[dx + kw], w1, acc[dx][1]);
                    }
                }
            }
        }
    }

    // fused AdaNorm + ReLU epilogue (norm over 32 couts held by 8 cg threads)
    float4 b4 = *(const float4*)(bias + co0);
    float rr[6][4];
#pragma unroll
    for (int dx = 0; dx < 6; dx++) {
        unpack2(acc[dx][0], rr[dx][0], rr[dx][1]);
        unpack2(acc[dx][1], rr[dx][2], rr[dx][3]);
        rr[dx][0] += b4.x; rr[dx][1] += b4.y; rr[dx][2] += b4.z; rr[dx][3] += b4.w;
    }
    __syncthreads();
    int vgrp = row * 8 + xt;       // 0..15
#pragma unroll
    for (int dx = 0; dx < 6; dx++) {
        float s1 = rr[dx][0] + rr[dx][1] + rr[dx][2] + rr[dx][3];
        float s2 = rr[dx][0] * rr[dx][0] + rr[dx][1] * rr[dx][1]
                 + rr[dx][2] * rr[dx][2] + rr[dx][3] * rr[dx][3];
        int idx = ((vgrp * 6 + dx) * 8 + cg) * 2;
        red[idx] = s1; red[idx + 1] = s2;
    }
    __syncthreads();
    float4 g4 = *(const float4*)(gvec + co0);
    const float4 z4 = make_float4(0.f, 0.f, 0.f, 0.f);
#pragma unroll
    for (int dx = 0; dx < 6; dx++) {
        float m = mout[vb + dx];
        float4 o4 = z4;
        if (m != 0.f) {
            float S1 = 0.f, S2 = 0.f;
#pragma unroll
            for (int c = 0; c < 8; c++) {
                int idx = ((vgrp * 6 + dx) * 8 + c) * 2;
                S1 += red[idx]; S2 += red[idx + 1];
            }
            float mean = S1 * (1.f / COUT);
            float var = S2 * (1.f / COUT) - mean * mean + EPS_;
            float rs = rsqrtf(var);
            float xn;
            xn = (rr[dx][0] - mean) * rs; o4.x = fmaxf(g4.x * (1.f - KADA * xn) * xn, 0.f);
            xn = (rr[dx][1] - mean) * rs; o4.y = fmaxf(g4.y * (1.f - KADA * xn) * xn, 0.f);
            xn = (rr[dx][2] - mean) * rs; o4.z = fmaxf(g4.z * (1.f - KADA * xn) * xn, 0.f);
            xn = (rr[dx][3] - mean) * rs; o4.w = fmaxf(g4.w * (1.f - KADA * xn) * xn, 0.f);
        }
        *reinterpret_cast<float4*>(out + (vb + dx) * COUT + co0) = o4;
    }
}

// ---------------------------------------------------------------------------
// Smem-staged conv (L4/L5) with fused AdaNorm+ReLU epilogue.
// Block = 128 thr = 2 y-rows x (XTC x-tiles x CGC cout-groups); 6x4 tiles.
// ---------------------------------------------------------------------------
template <int CIN, int GIN, int GOUT, int STRIDE, int COUT>
__global__ __launch_bounds__(128) void conv_smem_kernel(
    const float* __restrict__ in, const float* __restrict__ w,
    const float* __restrict__ bias, const float* __restrict__ gvec,
    const float* __restrict__ mout, float* __restrict__ out) {
    constexpr int XTC = GOUT / 6;
    constexpr int CGC = COUT / 4;
    static_assert(XTC * CGC == 64, "row must be 64 threads");
    constexpr int SPAN = GIN + 2;
    constexpr int SPANP = (SPAN & 1) ? SPAN : SPAN + 1;
    constexpr int NIN = (STRIDE == 1) ? 8 : 13;

    extern __shared__ ull smem[];
    ull* sinp = smem;                              // [2][CIN][SPANP]
    float* sw = (float*)(smem + 2 * CIN * SPANP);  // [3][CIN][COUT]
    float* red = (float*)smem;                     // epilogue overlay

    int tid = threadIdx.x;
    int row = tid >> 6;
    int r = tid & 63;
    int xt = r % XTC, cg = r / XTC;
    int x0 = xt * 6, co0 = cg * 4;

    int bid = blockIdx.x;
    int yp = bid % (GOUT / 2);
    int z = (bid / (GOUT / 2)) % GOUT;
    int b = bid / ((GOUT / 2) * GOUT);
    int y0 = yp * 2;

    size_t vb = (((size_t)b * GOUT + z) * GOUT + (y0 + row)) * (size_t)GOUT + x0;
    bool act = false;
#pragma unroll
    for (int dx = 0; dx < 6; dx++) act |= (mout[vb + dx] != 0.f);

    ull acc[6][2];
#pragma unroll
    for (int dx = 0; dx < 6; dx++) { acc[dx][0] = 0ULL; acc[dx][1] = 0ULL; }

    for (int kd = 0; kd < 3; kd++) {
        int iz = z * STRIDE + kd - 1;
        if (iz < 0 || iz >= GIN) continue;
        for (int kh = 0; kh < 3; kh++) {
            __syncthreads();
            // stage weights [kw][ci][co] (float4)
            for (int j = tid; j < 3 * CIN * (COUT / 4); j += 128) {
                int co4 = j % (COUT / 4);
                int ci = (j / (COUT / 4)) % CIN;
                int kw = j / ((COUT / 4) * CIN);
                float4 wv = *reinterpret_cast<const float4*>(
                    w + ((size_t)((kd * 3 + kh) * 3 + kw) * CIN + ci) * COUT + co4 * 4);
                *reinterpret_cast<float4*>(sw + (kw * CIN + ci) * COUT + co4 * 4) = wv;
            }
            // stage 2 input rows, paired, zero-filled OOB (float4 over ci)
            int iyb = y0 * STRIDE + kh - 1;
            for (int j = tid; j < 2 * (CIN / 4) * SPAN; j += 128) {
                int ci4 = j % (CIN / 4);
                int xp = (j / (CIN / 4)) % SPAN;
                int rw = j / ((CIN / 4) * SPAN);
                int iy = iyb + rw * STRIDE;
                int ix = xp - 1;
                float4 v4 = make_float4(0.f, 0.f, 0.f, 0.f);
                if ((unsigned)iy < (unsigned)GIN && (unsigned)ix < (unsigned)GIN)
                    v4 = *reinterpret_cast<const float4*>(
                        in + (((size_t)(b * GIN + iz) * GIN + iy) * GIN + ix) * CIN + ci4 * 4);
                ull* dst = sinp + (rw * CIN + ci4 * 4) * SPANP + xp;
                dst[0 * SPANP] = pack2(v4.x, v4.x);
                dst[1 * SPANP] = pack2(v4.y, v4.y);
                dst[2 * SPANP] = pack2(v4.z, v4.z);
                dst[3 * SPANP] = pack2(v4.w, v4.w);
            }
            __syncthreads();

            if (!act) continue;
            const ull* inr = sinp + row * (CIN * SPANP);
#pragma unroll 2
            for (int ci = 0; ci < CIN; ci++) {
                const ull* ip = inr + ci * SPANP + x0 * STRIDE;
                ull pk[NIN];
#pragma unroll
                for (int k = 0; k < NIN; k++) pk[k] = ip[k];
#pragma unroll
                for (int kw = 0; kw < 3; kw++) {
                    const ull* wv = (const ull*)(sw + (kw * CIN + ci) * COUT + co0);
                    ull w0 = wv[0], w1 = wv[1];
#pragma unroll
                    for (int dx = 0; dx < 6; dx++) {
                        acc[dx][0] = fma2(pk[dx * STRIDE + kw], w0, acc[dx][0]);
                        acc[dx][1] = fma2(pk[dx * STRIDE + kw], w1, acc[dx][1]);
                    }
                }
            }
        }
    }

    // fused AdaNorm + ReLU epilogue (norm over COUT held by CGC threads)
    float4 b4 = *(const float4*)(bias + co0);
    float rr[6][4];
#pragma unroll
    for (int dx = 0; dx < 6; dx++) {
        unpack2(acc[dx][0], rr[dx][0], rr[dx][1]);
        unpack2(acc[dx][1], rr[dx][2], rr[dx][3]);
        rr[dx][0] += b4.x; rr[dx][1] += b4.y; rr[dx][2] += b4.z; rr[dx][3] += b4.w;
    }
    __syncthreads();
    int vgrp = row * XTC + xt;
#pragma unroll
    for (int dx = 0; dx < 6; dx++) {
        float s1 = rr[dx][0] + rr[dx][1] + rr[dx][2] + rr[dx][3];
        float s2 = rr[dx][0] * rr[dx][0] + rr[dx][1] * rr[dx][1]
                 + rr[dx][2] * rr[dx][2] + rr[dx][3] * rr[dx][3];
        int idx = ((vgrp * 6 + dx) * CGC + cg) * 2;
        red[idx] = s1; red[idx + 1] = s2;
    }
    __syncthreads();
    float4 g4 = *(const float4*)(gvec + co0);
    const float4 z4 = make_float4(0.f, 0.f, 0.f, 0.f);
#pragma unroll
    for (int dx = 0; dx < 6; dx++) {
        float m = mout[vb + dx];
        float4 o4 = z4;
        if (m != 0.f) {
            float S1 = 0.f, S2 = 0.f;
#pragma unroll
            for (int c = 0; c < CGC; c++) {
                int idx = ((vgrp * 6 + dx) * CGC + c) * 2;
                S1 += red[idx]; S2 += red[idx + 1];
            }
            float mean = S1 * (1.f / COUT);
            float var = S2 * (1.f / COUT) - mean * mean + EPS_;
            float rs = rsqrtf(var);
            float xn;
            xn = (rr[dx][0] - mean) * rs; o4.x = fmaxf(g4.x * (1.f - KADA * xn) * xn, 0.f);
            xn = (rr[dx][1] - mean) * rs; o4.y = fmaxf(g4.y * (1.f - KADA * xn) * xn, 0.f);
            xn = (rr[dx][2] - mean) * rs; o4.z = fmaxf(g4.z * (1.f - KADA * xn) * xn, 0.f);
            xn = (rr[dx][3] - mean) * rs; o4.w = fmaxf(g4.w * (1.f - KADA * xn) * xn, 0.f);
        }
        *reinterpret_cast<float4*>(out + (vb + dx) * COUT + co0) = o4;
    }
}

// ---------------------------------------------------------------------------
// Global masked max pool -> d_pool[2][64]
// ---------------------------------------------------------------------------
__global__ void pool_kernel() {
    int b = blockIdx.x;
    int c = threadIdx.x & 63;
    int grp = threadIdx.x >> 6;
    float best = -3.0e38f;
    for (int v = grp; v < 13824; v += 16) {
        float m = d_m3[b * 13824 + v];
        float hv = d_h5[((size_t)(b * 13824 + v)) * 64 + c];
        best = fmaxf(best, m > 0.f ? hv : -3.0e38f);
    }
    __shared__ float red[1024];
    red[threadIdx.x] = best;
    __syncthreads();
    for (int s = 8; s > 0; s >>= 1) {
        if (grp < s) red[grp * 64 + c] = fmaxf(red[grp * 64 + c], red[(grp + s) * 64 + c]);
        __syncthreads();
    }
    if (grp == 0) d_pool[b * 64 + c] = red[c];
}

// ---------------------------------------------------------------------------
// Head
// ---------------------------------------------------------------------------
__global__ void head_kernel(const float* __restrict__ wh, const float* __restrict__ bh,
                            const float* __restrict__ gh, float* __restrict__ out) {
    int t = threadIdx.x;
    int b = t >> 6;
    int f = t & 63;
    float s = bh[f];
    for (int ci = 0; ci < 64; ci++) s += d_pool[b * 64 + ci] * wh[ci * 64 + f];
    __shared__ float sh[128];
    sh[t] = s;
    __syncthreads();
    float sum = 0.f;
    for (int j = 0; j < 64; j++) sum += sh[b * 64 + j];
    float mean = sum * (1.f / 64.f);
    float var = 0.f;
    for (int j = 0; j < 64; j++) { float d = sh[b * 64 + j] - mean; var += d * d; }
    float r = rsqrtf(var * (1.f / 64.f) + EPS_);
    float xn = (s - mean) * r;
    out[t] = fmaxf(gh[f] * (1.f - KADA * xn) * xn, 0.f);
}

// ---------------------------------------------------------------------------
// Launch
// ---------------------------------------------------------------------------
extern "C" void kernel_launch(void* const* d_in, const int* in_sizes, int n_in,
                              void* d_out, int out_size) {
    const float* x    = (const float*)d_in[0];
    const float* mask = (const float*)d_in[1];
    const float* w1 = (const float*)d_in[2];
    const float* b1 = (const float*)d_in[3];
    const float* g1 = (const float*)d_in[4];
    const float* w2 = (const float*)d_in[5];
    const float* b2 = (const float*)d_in[6];
    const float* g2 = (const float*)d_in[7];
    const float* w3 = (const float*)d_in[8];
    const float* b3 = (const float*)d_in[9];
    const float* g3 = (const float*)d_in[10];
    const float* w4 = (const float*)d_in[11];
    const float* b4 = (const float*)d_in[12];
    const float* g4 = (const float*)d_in[13];
    const float* w5 = (const float*)d_in[14];
    const float* b5 = (const float*)d_in[15];
    const float* g5 = (const float*)d_in[16];
    const float* wh = (const float*)d_in[17];
    const float* bh = (const float*)d_in[18];
    const float* gh = (const float*)d_in[19];
    float* out = (float*)d_out;

    cudaFuncSetAttribute(l2_kernel, cudaFuncAttributeMaxDynamicSharedMemorySize, 56 * 1024);
    cudaFuncSetAttribute(conv3_kernel, cudaFuncAttributeMaxDynamicSharedMemorySize, 92 * 1024);
    cudaFuncSetAttribute(conv_smem_kernel<32, 48, 24, 2, 64>,
                         cudaFuncAttributeMaxDynamicSharedMemorySize, 52 * 1024);
    cudaFuncSetAttribute(conv_smem_kernel<64, 24, 24, 1, 64>,
                         cudaFuncAttributeMaxDynamicSharedMemorySize, 78 * 1024);

    void *ph2, *ph3, *ph4, *ph5, *pm2, *pm3;
    cudaGetSymbolAddress(&ph2, d_h2);
    cudaGetSymbolAddress(&ph3, d_h3);
    cudaGetSymbolAddress(&ph4, d_h4);
    cudaGetSymbolAddress(&ph5, d_h5);
    cudaGetSymbolAddress(&pm2, d_m2);
    cudaGetSymbolAddress(&pm3, d_m3);

    // masks
    downsample_kernel<96, 48><<<(2 * 48 * 48 * 48 + 255) / 256, 256>>>(mask, (float*)pm2);
    downsample_kernel<48, 24><<<(2 * 24 * 24 * 24 + 255) / 256, 256>>>((const float*)pm2, (float*)pm3);

    // layer 1 (fused; active sites only)
    l1_kernel<<<2 * 96 * 96 * 96 / 128, 128>>>(x, mask, w1, b1, g1);

    // layer 2 (fused, ballot tap discovery, 2-voxel ILP)
    l2_kernel<<<592, 256, (13824 + 64) * 4>>>(mask, w2, b2, g2);

    // layer 3: 48^3, 32->32, s=1, per-kd staging + fused norm
    constexpr int SM3 = 4 * 32 * 51 * 8 + 9 * 32 * 32 * 4;   // 89088
    conv3_kernel<<<24 * 48 * 2, 128, SM3>>>(
        (const float*)ph2, w3, b3, g3, (const float*)pm2, (float*)ph3);

    // layer 4: 48^3 -> 24^3, 32->64, s=2, fused norm
    constexpr int SM4 = 2 * 32 * 51 * 8 + 3 * 32 * 64 * 4;   // 50688
    conv_smem_kernel<32, 48, 24, 2, 64><<<12 * 24 * 2, 128, SM4>>>(
        (const float*)ph3, w4, b4, g4, (const float*)pm3, (float*)ph4);

    // layer 5: 24^3, 64->64, s=1, fused norm
    constexpr int SM5 = 2 * 64 * 27 * 8 + 3 * 64 * 64 * 4;   // 76800
    conv_smem_kernel<64, 24, 24, 1, 64><<<12 * 24 * 2, 128, SM5>>>(
        (const float*)ph4, w5, b5, g5, (const float*)pm3, (float*)ph5);

    // pool + head
    pool_kernel<<<2, 1024>>>();
    head_kernel<<<1, 128>>>(wh, bh, gh, out);
}